// round 17
// baseline (speedup 1.0000x reference)
#include <cuda_runtime.h>
#include <cuda.h>
#include <cuda_fp16.h>
#include <cstdint>
#include <math.h>

// B=64, S=512, Q=800, K=4, D=64  ->  GEMM: C[M=32768, N=64] = A[M,800] * Wq^T[800,64]
#define MDIM    32768
#define KDIM    800
#define NDIM    64
#define TMR     64            // rows per tile
#define NTILES  (MDIM / TMR)  // 512
#define TK      32
#define NIT     25
#define THREADS 256
#define NCTAS   296           // 2 per SM exactly
#define STAGES  4

#define A_BYTES (TMR * TK * 4)           // 8192 (raw f32, SW128)
#define B_BYTES (NDIM * TK * 2)          // 4096 (f16 fragment image)
#define STAGE_BYTES (A_BYTES + B_BYTES)  // 12288
#define OFF_MBAR   (STAGES * STAGE_BYTES)        // 49152
#define OFF_TILE   (OFF_MBAR + STAGES * 8)       // 49184 (tile broadcast word)
#define SMEM_TOTAL (OFF_TILE + 16)               // 49200

// B as f16 mma fragments, lane-indexed for conflict-free LDS.128 (same image
// as R14): word idx = ((s*2 + kt)*4 + j)*128 + lane*4 + w
__device__ uint32_t g_Bt[NIT * 1024];    // 102.4 KB
__device__ int g_ctr;                    // work-stealing tile counter

// ---------------------------------------------------------------------------
// helpers
// ---------------------------------------------------------------------------
__device__ __forceinline__ uint32_t cvt_f16x2(float lo, float hi) {
    uint32_t r;
    asm("cvt.rn.f16x2.f32 %0, %1, %2;" : "=r"(r) : "f"(hi), "f"(lo));
    return r;
}

__device__ __forceinline__ float2 lds64(uint32_t addr) {
    float2 v;
    asm volatile("ld.shared.v2.f32 {%0, %1}, [%2];"
                 : "=f"(v.x), "=f"(v.y) : "r"(addr));
    return v;
}

__device__ __forceinline__ void lds128(uint32_t* r, uint32_t addr) {
    asm volatile("ld.shared.v4.b32 {%0, %1, %2, %3}, [%4];"
                 : "=r"(r[0]), "=r"(r[1]), "=r"(r[2]), "=r"(r[3]) : "r"(addr));
}

__device__ __forceinline__ void mma_f16(float* c,
                                        uint32_t a0, uint32_t a1, uint32_t a2, uint32_t a3,
                                        uint32_t b0, uint32_t b1) {
    asm volatile(
        "mma.sync.aligned.m16n8k16.row.col.f32.f16.f16.f32 "
        "{%0,%1,%2,%3}, {%4,%5,%6,%7}, {%8,%9}, {%0,%1,%2,%3};"
        : "+f"(c[0]), "+f"(c[1]), "+f"(c[2]), "+f"(c[3])
        : "r"(a0), "r"(a1), "r"(a2), "r"(a3), "r"(b0), "r"(b1));
}

__device__ __forceinline__ void mbar_wait(uint32_t mbar, uint32_t parity) {
    asm volatile(
        "{\n\t"
        ".reg .pred P1;\n\t"
        "WAIT_LOOP_%=:\n\t"
        "mbarrier.try_wait.parity.acquire.cta.shared::cta.b64 P1, [%0], %1, 0x989680;\n\t"
        "@P1 bra.uni WAIT_DONE_%=;\n\t"
        "bra.uni WAIT_LOOP_%=;\n\t"
        "WAIT_DONE_%=:\n\t"
        "}"
        :: "r"(mbar), "r"(parity) : "memory");
}

// ---------------------------------------------------------------------------
// pre-kernel: Wq -> f16 fragment image + reset the steal counter
// ---------------------------------------------------------------------------
__global__ void convert_B_kernel(const float* __restrict__ Wq) {
    if (blockIdx.x == 0 && threadIdx.x == 0) g_ctr = 0;
    int i = blockIdx.x * 256 + threadIdx.x;
    if (i < NIT * 1024) {
        int w_ = i & 3;
        int l  = (i >> 2) & 31;
        int j  = (i >> 7) & 3;
        int kt = (i >> 9) & 1;
        int s  = i >> 10;
        int nt = j * 2 + (w_ >> 1);
        int b  = w_ & 1;
        int n  = nt * 8 + (l >> 2);
        int k  = s * 32 + kt * 16 + b * 8 + (l & 3) * 2;
        uint32_t lo = __half_as_ushort(__float2half_rn(Wq[n * KDIM + k]));
        uint32_t hi = __half_as_ushort(__float2half_rn(Wq[n * KDIM + k + 1]));
        g_Bt[i] = (hi << 16) | lo;
    }
}

// ---------------------------------------------------------------------------
// main kernel: persistent CTAs stealing 64-row tiles; warp = 16 rows x 32 cols
// ---------------------------------------------------------------------------
__global__ __launch_bounds__(THREADS, 2)
void ordinal_embed_kernel(const __grid_constant__ CUtensorMap tmapA,
                          const __grid_constant__ CUtensorMap tmapB,
                          const int*   __restrict__ rdat,
                          const float* __restrict__ bq,   // [64]
                          const float* __restrict__ Wr,   // [4]
                          const float* __restrict__ br,   // [1]
                          float*       __restrict__ out)  // [32768, 64]
{
    // NO static __shared__ here — it would shift the dynamic base off the
    // 1024-byte alignment TMA SW128 needs (the R15 misaligned-address bug).
    extern __shared__ __align__(1024) uint8_t smem[];
    const uint32_t smemBase = (uint32_t)__cvta_generic_to_shared(smem);
    int* s_tile = reinterpret_cast<int*>(smem + OFF_TILE);

    const int tid  = threadIdx.x;
    const int lane = tid & 31;
    const int w    = tid >> 5;         // 0..7
    const int mg   = w & 3;            // rows  [mg*16, mg*16+16) within tile
    const int nh   = w >> 2;           // cols  [nh*32, nh*32+32)

    // ---- mbarrier init ------------------------------------------------------
    if (tid == 0) {
        #pragma unroll
        for (int s = 0; s < STAGES; ++s)
            asm volatile("mbarrier.init.shared.b64 [%0], %1;"
                         :: "r"(smemBase + OFF_MBAR + s * 8), "r"(1u) : "memory");
        asm volatile("fence.proxy.async.shared::cta;" ::: "memory");
    }
    __syncthreads();

    // ---- per-lane A fragment coordinates -----------------------------------
    const int mA  = mg * 16 + (lane >> 2);
    const int kpl = (lane & 3) * 2;
    const int xm  = (mA & 7) * 16;               // same for mA+8
    const uint32_t rowOff0 = (uint32_t)mA * 128u;
    const uint32_t rowOff1 = (uint32_t)(mA + 8) * 128u;

    const float wr0 = Wr[0], wr1 = Wr[1], wr2 = Wr[2], wr3 = Wr[3];
    const float brv = br[0];

    int gs = 0;   // global stage counter (uniform across the CTA)

    while (true) {
        if (tid == 0) *s_tile = atomicAdd(&g_ctr, 1);
        __syncthreads();                 // also fences prior tile's consumers
        const int t = *s_tile;
        if (t >= NTILES) break;
        const int row0 = t * TMR;

        float acc[4][4];
        #pragma unroll
        for (int nt = 0; nt < 4; ++nt)
            #pragma unroll
            for (int i = 0; i < 4; ++i)
                acc[nt][i] = 0.0f;

        // ---- prologue: 3 stages --------------------------------------------
        if (tid == 0) {
            #pragma unroll
            for (int p = 0; p < STAGES - 1; ++p) {
                const int slot = (gs + p) & 3;
                const uint32_t mb = smemBase + OFF_MBAR + slot * 8;
                const uint32_t sbp = smemBase + slot * STAGE_BYTES;
                asm volatile("mbarrier.arrive.expect_tx.shared.b64 _, [%0], %1;"
                             :: "r"(mb), "r"((uint32_t)STAGE_BYTES) : "memory");
                asm volatile(
                    "cp.async.bulk.tensor.2d.shared::cta.global.tile"
                    ".mbarrier::complete_tx::bytes [%0], [%1, {%2, %3}], [%4];"
                    :: "r"(sbp), "l"(&tmapA), "r"(p * TK), "r"(row0),
                       "r"(mb) : "memory");
                asm volatile(
                    "cp.async.bulk.tensor.2d.shared::cta.global.tile"
                    ".mbarrier::complete_tx::bytes [%0], [%1, {%2, %3}], [%4];"
                    :: "r"(sbp + A_BYTES), "l"(&tmapB), "r"(0), "r"(p * 4),
                       "r"(mb) : "memory");
            }
        }

        for (int it = 0; it < NIT; ++it) {
            const int c = gs + it;
            mbar_wait(smemBase + OFF_MBAR + (c & 3) * 8, (uint32_t)((c >> 2) & 1));
            __syncthreads();   // compute(it-1) complete -> slot (c+3)&3 reusable

            if (tid == 0 && it + STAGES - 1 < NIT) {
                const int cc = c + STAGES - 1;
                const int slot = cc & 3;
                const uint32_t mb = smemBase + OFF_MBAR + slot * 8;
                const uint32_t sbp = smemBase + slot * STAGE_BYTES;
                asm volatile("mbarrier.arrive.expect_tx.shared.b64 _, [%0], %1;"
                             :: "r"(mb), "r"((uint32_t)STAGE_BYTES) : "memory");
                asm volatile(
                    "cp.async.bulk.tensor.2d.shared::cta.global.tile"
                    ".mbarrier::complete_tx::bytes [%0], [%1, {%2, %3}], [%4];"
                    :: "r"(sbp), "l"(&tmapA), "r"((it + STAGES - 1) * TK),
                       "r"(row0), "r"(mb) : "memory");
                asm volatile(
                    "cp.async.bulk.tensor.2d.shared::cta.global.tile"
                    ".mbarrier::complete_tx::bytes [%0], [%1, {%2, %3}], [%4];"
                    :: "r"(sbp + A_BYTES), "l"(&tmapB), "r"(0),
                       "r"((it + STAGES - 1) * 4), "r"(mb) : "memory");
            }

            const uint32_t sb = smemBase + (uint32_t)(c & 3) * STAGE_BYTES;
            const uint32_t aB = sb;
            const uint32_t bB = sb + A_BYTES;

            #pragma unroll
            for (int kt = 0; kt < 2; ++kt) {
                // B fragments for this warp's 32 cols: 2 conflict-free LDS.128
                uint32_t bf[2][4];
                #pragma unroll
                for (int jj = 0; jj < 2; ++jj)
                    lds128(bf[jj], bB + (uint32_t)(((kt * 4 + nh * 2 + jj) * 512)
                                                   + lane * 16));

                // A fragments: 4 x (LDS.64 + cvt.f16x2)
                const int k0 = kt * 16 + kpl;
                float2 v00 = lds64(aB + rowOff0 + (uint32_t)((k0 * 4) ^ xm));
                float2 v10 = lds64(aB + rowOff1 + (uint32_t)((k0 * 4) ^ xm));
                float2 v01 = lds64(aB + rowOff0 + (uint32_t)(((k0 + 8) * 4) ^ xm));
                float2 v11 = lds64(aB + rowOff1 + (uint32_t)(((k0 + 8) * 4) ^ xm));
                uint32_t a0 = cvt_f16x2(v00.x, v00.y);
                uint32_t a1 = cvt_f16x2(v10.x, v10.y);
                uint32_t a2 = cvt_f16x2(v01.x, v01.y);
                uint32_t a3 = cvt_f16x2(v11.x, v11.y);

                #pragma unroll
                for (int nt = 0; nt < 4; ++nt)
                    mma_f16(acc[nt], a0, a1, a2, a3,
                            bf[nt >> 1][(nt & 1) * 2], bf[nt >> 1][(nt & 1) * 2 + 1]);
            }
        }
        gs += NIT;

        // ---- epilogue: gate(r) * acc + bq (registers + gmem only) ----------
        const int rbase = row0 + mg * 16 + (lane >> 2);
        #pragma unroll
        for (int h = 0; h < 2; ++h) {
            const int row = rbase + h * 8;
            const float rf = (float)rdat[row];
            float s = brv;
            s += fmaxf(1.0f - fabsf(0.0f - rf) * (1.0f / 3.0f), 0.0f) * wr0;
            s += fmaxf(1.0f - fabsf(1.0f - rf) * (1.0f / 3.0f), 0.0f) * wr1;
            s += fmaxf(1.0f - fabsf(2.0f - rf) * (1.0f / 3.0f), 0.0f) * wr2;
            s += fmaxf(1.0f - fabsf(3.0f - rf) * (1.0f / 3.0f), 0.0f) * wr3;
            const float gate = 1.0f / (1.0f + expf(-s));

            #pragma unroll
            for (int nt = 0; nt < 4; ++nt) {
                const int col = nh * 32 + nt * 8 + (lane & 3) * 2;
                float2 v;
                v.x = acc[nt][h * 2 + 0] * gate + bq[col];
                v.y = acc[nt][h * 2 + 1] * gate + bq[col + 1];
                *reinterpret_cast<float2*>(out + (size_t)row * NDIM + col) = v;
            }
        }
    }
}

// ---------------------------------------------------------------------------
// launch
// ---------------------------------------------------------------------------
typedef CUresult (*EncodeTiledFn)(
    CUtensorMap*, CUtensorMapDataType, cuuint32_t, void*,
    const cuuint64_t*, const cuuint64_t*, const cuuint32_t*, const cuuint32_t*,
    CUtensorMapInterleave, CUtensorMapSwizzle, CUtensorMapL2promotion,
    CUtensorMapFloatOOBfill);

extern "C" void kernel_launch(void* const* d_in, const int* in_sizes, int n_in,
                              void* d_out, int out_size) {
    const float* q    = (const float*)d_in[0];   // [64,512,800] f32
    const int*   rdat = (const int*)  d_in[1];   // [64,512]     i32
    const float* Wq   = (const float*)d_in[2];   // [64,800]     f32
    const float* bq   = (const float*)d_in[3];   // [64]         f32
    const float* Wr   = (const float*)d_in[4];   // [1,4]        f32
    const float* br   = (const float*)d_in[5];   // [1]          f32
    float* out = (float*)d_out;                  // [64,512,64]  f32

    static EncodeTiledFn encode = nullptr;
    if (!encode) {
        cudaDriverEntryPointQueryResult st;
        void* fn = nullptr;
        cudaGetDriverEntryPoint("cuTensorMapEncodeTiled", &fn,
                                cudaEnableDefault, &st);
        encode = (EncodeTiledFn)fn;
    }

    void* bImg = nullptr;
    cudaGetSymbolAddress(&bImg, g_Bt);

    // A: [KDIM, MDIM] f32, box [32, 64], SW128
    CUtensorMap tmapA{};
    {
        cuuint64_t dims[2]    = {KDIM, MDIM};
        cuuint64_t strides[1] = {KDIM * 4ull};
        cuuint32_t box[2]     = {TK, TMR};
        cuuint32_t estr[2]    = {1, 1};
        encode(&tmapA, CU_TENSOR_MAP_DATA_TYPE_FLOAT32, 2, (void*)q,
               dims, strides, box, estr,
               CU_TENSOR_MAP_INTERLEAVE_NONE, CU_TENSOR_MAP_SWIZZLE_128B,
               CU_TENSOR_MAP_L2_PROMOTION_L2_256B,
               CU_TENSOR_MAP_FLOAT_OOB_FILL_NONE);
    }
    // B image: [256, 100] u32, box [256, 4], no swizzle
    CUtensorMap tmapB{};
    {
        cuuint64_t dims[2]    = {256, (cuuint64_t)(NIT * 4)};
        cuuint64_t strides[1] = {256 * 4ull};
        cuuint32_t box[2]     = {256, 4};
        cuuint32_t estr[2]    = {1, 1};
        encode(&tmapB, CU_TENSOR_MAP_DATA_TYPE_FLOAT32, 2, bImg,
               dims, strides, box, estr,
               CU_TENSOR_MAP_INTERLEAVE_NONE, CU_TENSOR_MAP_SWIZZLE_NONE,
               CU_TENSOR_MAP_L2_PROMOTION_L2_256B,
               CU_TENSOR_MAP_FLOAT_OOB_FILL_NONE);
    }

    convert_B_kernel<<<(NIT * 1024 + 255) / 256, 256>>>(Wq);

    cudaFuncSetAttribute(ordinal_embed_kernel,
                         cudaFuncAttributeMaxDynamicSharedMemorySize, SMEM_TOTAL);
    ordinal_embed_kernel<<<NCTAS, THREADS, SMEM_TOTAL>>>(
        tmapA, tmapB, rdat, bq, Wr, br, out);
}